// round 1
// baseline (speedup 1.0000x reference)
#include <cuda_runtime.h>
#include <math.h>

// Problem constants
#define NN 100000
#define EE 600000
#define IND 128
#define HIDD 128
#define OUTD 64

// ---------------- device scratch (no allocations allowed) ----------------
__device__ int   g_deg[NN];
__device__ int   g_rowptr[NN + 1];
__device__ int   g_cursor[NN];
__device__ int   g_col[EE];
__device__ float g_dinv[NN];
__device__ int   g_partial[512];
__device__ float g_t1[NN * HIDD];   // g1 = (x@W1)*dinv
__device__ float g_h [NN * HIDD];   // layer-1 output (post agg, +b1, relu)
__device__ float g_t2[NN * OUTD];   // g2 = (h@W2)*dinv

static constexpr int SCAN_NB = (NN + 255) / 256;   // 391

// ---------------- preprocessing: degree + CSR ----------------
__global__ void k_zero_deg() {
    int i = blockIdx.x * blockDim.x + threadIdx.x;
    if (i < NN) g_deg[i] = 0;
}

__global__ void k_count(const int* __restrict__ dst) {
    int e = blockIdx.x * blockDim.x + threadIdx.x;
    if (e < EE) atomicAdd(&g_deg[dst[e]], 1);
}

__global__ void k_partial() {
    __shared__ int s[256];
    int t = threadIdx.x;
    int i = blockIdx.x * 256 + t;
    s[t] = (i < NN) ? g_deg[i] : 0;
    __syncthreads();
    for (int o = 128; o > 0; o >>= 1) {
        if (t < o) s[t] += s[t + o];
        __syncthreads();
    }
    if (t == 0) g_partial[blockIdx.x] = s[0];
}

__global__ void k_scan_partial() {   // 1 block, 512 threads
    __shared__ int s[512];
    int t = threadIdx.x;
    int own = (t < SCAN_NB) ? g_partial[t] : 0;
    s[t] = own;
    __syncthreads();
    for (int o = 1; o < 512; o <<= 1) {
        int v = s[t];
        if (t >= o) v += s[t - o];
        __syncthreads();
        s[t] = v;
        __syncthreads();
    }
    if (t < SCAN_NB) g_partial[t] = s[t] - own;   // exclusive
}

__global__ void k_finalize() {
    __shared__ int s[256];
    int t = threadIdx.x;
    int i = blockIdx.x * 256 + t;
    int d = (i < NN) ? g_deg[i] : 0;
    s[t] = d;
    __syncthreads();
    for (int o = 1; o < 256; o <<= 1) {
        int v = s[t];
        if (t >= o) v += s[t - o];
        __syncthreads();
        s[t] = v;
        __syncthreads();
    }
    if (i < NN) {
        int excl = g_partial[blockIdx.x] + s[t] - d;
        g_rowptr[i] = excl;
        g_cursor[i] = excl;
        g_dinv[i]   = rsqrtf((float)(d + 1));   // +1 self-loop, always > 0
    }
    if (blockIdx.x == 0 && t == 0) g_rowptr[NN] = EE;
}

__global__ void k_fill(const int* __restrict__ src, const int* __restrict__ dst) {
    int e = blockIdx.x * blockDim.x + threadIdx.x;
    if (e < EE) {
        int p = atomicAdd(&g_cursor[dst[e]], 1);
        g_col[p] = src[e];
    }
}

// ---------------- dense: g[i] = (X[i] @ W) * dinv[i] ----------------
// X: [NN, 128], W: [128, F]. K=128 fits entirely in smem (no k-tiling).
template <int F>
__global__ void k_gemm_scale(const float* __restrict__ X,
                             const float* __restrict__ W,
                             float* __restrict__ out) {
    constexpr int K    = 128;
    constexpr int ROWS = 64;
    constexpr int BS   = 256;
    constexpr int TC   = F / 4;       // col-threads (each owns 4 cols)
    constexpr int TR   = BS / TC;     // row-threads
    constexpr int RPT  = ROWS / TR;   // rows per thread
    constexpr int XSTR = K + 4;       // padded x row stride (bank spread)

    extern __shared__ float sm[];
    float* Ws = sm;               // K * F
    float* Xs = sm + K * F;       // ROWS * XSTR

    const int t    = threadIdx.x;
    const int row0 = blockIdx.x * ROWS;

    // load W (coalesced float4)
    for (int i = t; i < K * F / 4; i += BS)
        ((float4*)Ws)[i] = ((const float4*)W)[i];

    // load X tile (coalesced float4, guarded)
    for (int i = t; i < ROWS * (K / 4); i += BS) {
        int r  = i / (K / 4);
        int c  = i % (K / 4);
        int gr = row0 + r;
        float4 v = (gr < NN) ? ((const float4*)(X + (size_t)gr * K))[c]
                             : make_float4(0.f, 0.f, 0.f, 0.f);
        ((float4*)(Xs + r * XSTR))[c] = v;
    }
    __syncthreads();

    const int ct    = t % TC;
    const int rt    = t / TC;
    const int rbase = rt * RPT;
    const int ct4   = ct * 4;

    float acc[RPT][4];
#pragma unroll
    for (int r = 0; r < RPT; r++)
#pragma unroll
        for (int c = 0; c < 4; c++) acc[r][c] = 0.f;

#pragma unroll 4
    for (int k = 0; k < K; k++) {
        float4 wv = *(const float4*)(Ws + k * F + ct4);
        float xv[RPT];
#pragma unroll
        for (int r = 0; r < RPT; r++) xv[r] = Xs[(rbase + r) * XSTR + k];
#pragma unroll
        for (int r = 0; r < RPT; r++) {
            acc[r][0] = fmaf(xv[r], wv.x, acc[r][0]);
            acc[r][1] = fmaf(xv[r], wv.y, acc[r][1]);
            acc[r][2] = fmaf(xv[r], wv.z, acc[r][2]);
            acc[r][3] = fmaf(xv[r], wv.w, acc[r][3]);
        }
    }

#pragma unroll
    for (int r = 0; r < RPT; r++) {
        int gr = row0 + rbase + r;
        if (gr < NN) {
            float d = g_dinv[gr];
            float4 o = make_float4(acc[r][0] * d, acc[r][1] * d,
                                   acc[r][2] * d, acc[r][3] * d);
            *(float4*)(out + (size_t)gr * F + ct4) = o;
        }
    }
}

// ---------------- sparse aggregate: out[i] = dinv[i]*(sum g[src] + g[i]) + b ----
// one warp per node; F=128 -> float4/lane, F=64 -> float2/lane
template <int F, bool RELU>
__global__ void k_agg(const float* __restrict__ g,
                      const float* __restrict__ bias,
                      float* __restrict__ out) {
    constexpr int VEC = F / 32;   // 4 or 2
    int wid  = (blockIdx.x * blockDim.x + threadIdx.x) >> 5;
    int lane = threadIdx.x & 31;
    if (wid >= NN) return;

    const float* self = g + (size_t)wid * F + lane * VEC;
    float a[VEC];
    if (VEC == 4) {
        float4 v = *(const float4*)self;
        a[0] = v.x; a[1] = v.y; a[2] = v.z; a[3] = v.w;
    } else {
        float2 v = *(const float2*)self;
        a[0] = v.x; a[1] = v.y;
    }

    int s0 = g_rowptr[wid];
    int s1 = g_rowptr[wid + 1];
    for (int j = s0; j < s1; j++) {
        int s = g_col[j];                       // broadcast load
        const float* p = g + (size_t)s * F + lane * VEC;
        if (VEC == 4) {
            float4 v = *(const float4*)p;
            a[0] += v.x; a[1] += v.y; a[2] += v.z; a[3] += v.w;
        } else {
            float2 v = *(const float2*)p;
            a[0] += v.x; a[1] += v.y;
        }
    }

    float d = g_dinv[wid];
    float* op = out + (size_t)wid * F + lane * VEC;
    if (VEC == 4) {
        float4 b = *(const float4*)(bias + lane * 4);
        float4 o = make_float4(a[0] * d + b.x, a[1] * d + b.y,
                               a[2] * d + b.z, a[3] * d + b.w);
        if (RELU) {
            o.x = fmaxf(o.x, 0.f); o.y = fmaxf(o.y, 0.f);
            o.z = fmaxf(o.z, 0.f); o.w = fmaxf(o.w, 0.f);
        }
        *(float4*)op = o;
    } else {
        float2 b = *(const float2*)(bias + lane * 2);
        float2 o = make_float2(a[0] * d + b.x, a[1] * d + b.y);
        if (RELU) { o.x = fmaxf(o.x, 0.f); o.y = fmaxf(o.y, 0.f); }
        *(float2*)op = o;
    }
}

// ---------------- launch ----------------
extern "C" void kernel_launch(void* const* d_in, const int* in_sizes, int n_in,
                              void* d_out, int out_size) {
    const float* x  = (const float*)d_in[0];
    const int*   ei = (const int*)d_in[1];     // [2, E] row-major
    const float* W1 = (const float*)d_in[2];
    const float* b1 = (const float*)d_in[3];
    const float* W2 = (const float*)d_in[4];
    const float* b2 = (const float*)d_in[5];
    float* out = (float*)d_out;

    const int* src = ei;
    const int* dst = ei + EE;

    // opt-in smem (idempotent host calls; not captured)
    const int SM1 = (128 * HIDD + 64 * (128 + 4)) * 4;   // 99,328 B
    const int SM2 = (128 * OUTD + 64 * (128 + 4)) * 4;   // 66,560 B
    cudaFuncSetAttribute(k_gemm_scale<HIDD>,
                         cudaFuncAttributeMaxDynamicSharedMemorySize, SM1);
    cudaFuncSetAttribute(k_gemm_scale<OUTD>,
                         cudaFuncAttributeMaxDynamicSharedMemorySize, SM2);

    // CSR + dinv (rebuilt every call: deterministic work)
    k_zero_deg<<<(NN + 255) / 256, 256>>>();
    k_count<<<(EE + 255) / 256, 256>>>(dst);
    k_partial<<<SCAN_NB, 256>>>();
    k_scan_partial<<<1, 512>>>();
    k_finalize<<<SCAN_NB, 256>>>();
    k_fill<<<(EE + 255) / 256, 256>>>(src, dst);

    const int gemm_grid = (NN + 63) / 64;   // 1563
    const int agg_grid  = (NN * 32 + 255) / 256;   // 12500

    // layer 1
    k_gemm_scale<HIDD><<<gemm_grid, 256, SM1>>>(x, W1, g_t1);
    k_agg<HIDD, true><<<agg_grid, 256>>>(g_t1, b1, g_h);
    // layer 2
    k_gemm_scale<OUTD><<<gemm_grid, 256, SM2>>>(g_h, W2, g_t2);
    k_agg<OUTD, false><<<agg_grid, 256>>>(g_t2, b2, out);
}

// round 3
// speedup vs baseline: 1.0026x; 1.0026x over previous
#include <cuda_runtime.h>
#include <math.h>

// Problem constants
#define NN 100000
#define EE 600000
#define IND 128
#define HIDD 128
#define OUTD 64

// ---------------- device scratch (no allocations allowed) ----------------
__device__ int   g_deg[NN];
__device__ int   g_rowptr[NN + 1];
__device__ int   g_cursor[NN];
__device__ int   g_col[EE];
__device__ float g_dinv[NN];
__device__ int   g_partial[512];
__device__ float g_t1[NN * HIDD];   // h1 = x@W1 (unscaled)
__device__ float g_h [NN * HIDD];   // layer-1 output (post agg, +b1, relu)
__device__ float g_t2[NN * OUTD];   // h2 = h@W2 (unscaled)

static constexpr int SCAN_NB = (NN + 255) / 256;   // 391

// ---------------- preprocessing: degree + CSR ----------------
__global__ void k_zero_deg() {
    int i = blockIdx.x * blockDim.x + threadIdx.x;
    if (i < NN) g_deg[i] = 0;
}

__global__ void k_count(const int* __restrict__ dst) {
    int e = blockIdx.x * blockDim.x + threadIdx.x;
    if (e < EE) atomicAdd(&g_deg[dst[e]], 1);
}

__global__ void k_partial() {
    __shared__ int s[256];
    int t = threadIdx.x;
    int i = blockIdx.x * 256 + t;
    s[t] = (i < NN) ? g_deg[i] : 0;
    __syncthreads();
    for (int o = 128; o > 0; o >>= 1) {
        if (t < o) s[t] += s[t + o];
        __syncthreads();
    }
    if (t == 0) g_partial[blockIdx.x] = s[0];
}

__global__ void k_scan_partial() {   // 1 block, 512 threads
    __shared__ int s[512];
    int t = threadIdx.x;
    int own = (t < SCAN_NB) ? g_partial[t] : 0;
    s[t] = own;
    __syncthreads();
    for (int o = 1; o < 512; o <<= 1) {
        int v = s[t];
        if (t >= o) v += s[t - o];
        __syncthreads();
        s[t] = v;
        __syncthreads();
    }
    if (t < SCAN_NB) g_partial[t] = s[t] - own;   // exclusive
}

__global__ void k_finalize() {
    __shared__ int s[256];
    int t = threadIdx.x;
    int i = blockIdx.x * 256 + t;
    int d = (i < NN) ? g_deg[i] : 0;
    s[t] = d;
    __syncthreads();
    for (int o = 1; o < 256; o <<= 1) {
        int v = s[t];
        if (t >= o) v += s[t - o];
        __syncthreads();
        s[t] = v;
        __syncthreads();
    }
    if (i < NN) {
        int excl = g_partial[blockIdx.x] + s[t] - d;
        g_rowptr[i] = excl;
        g_cursor[i] = excl;
        g_dinv[i]   = rsqrtf((float)(d + 1));   // +1 self-loop, always > 0
    }
    if (blockIdx.x == 0 && t == 0) g_rowptr[NN] = EE;
}

__global__ void k_fill(const int* __restrict__ src, const int* __restrict__ dst) {
    int e = blockIdx.x * blockDim.x + threadIdx.x;
    if (e < EE) {
        int p = atomicAdd(&g_cursor[dst[e]], 1);
        g_col[p] = src[e];
    }
}

// ---------------- dense: H = X @ W (f32x2 packed along K) ----------------
// X: [NN, 128], W: [128, F]. Accumulators hold (even-k, odd-k) partial sums.
__device__ __forceinline__ void ffma2(unsigned long long& d,
                                      unsigned long long a,
                                      unsigned long long b) {
    asm("fma.rn.f32x2 %0, %1, %2, %0;" : "+l"(d) : "l"(a), "l"(b));
}

template <int F>
__global__ void k_gemm(const float* __restrict__ X,
                       const float* __restrict__ W,
                       float* __restrict__ out) {
    constexpr int K    = 128;
    constexpr int ROWS = 64;
    constexpr int BS   = 256;
    constexpr int TC   = F / 4;       // each thread owns cols ct + i*TC, i=0..3
    constexpr int TR   = BS / TC;
    constexpr int RPT  = ROWS / TR;   // 8 (F=128) or 4 (F=64)
    // XSTR must be divisible by 4 (float4 tile stores land 16B-aligned at any
    // row) and even (LDS.64 reads at +2*k2 stay 8B-aligned).  K+4 = 132. ✔
    constexpr int XSTR = K + 4;

    extern __shared__ float sm[];
    float2* Wq = (float2*)sm;         // [(K/2) * F] k-pair-interleaved
    float*  Xs = sm + K * F;          // ROWS * XSTR, row-major

    const int t    = threadIdx.x;
    const int row0 = blockIdx.x * ROWS;

    // build Wq: Wq[k2*F + c] = (W[2k2][c], W[2k2+1][c])
    for (int i = t; i < (K / 2) * (F / 4); i += BS) {
        int k2 = i / (F / 4);
        int c4 = (i % (F / 4)) * 4;
        float4 a = *(const float4*)(W + (size_t)(2 * k2) * F + c4);
        float4 b = *(const float4*)(W + (size_t)(2 * k2 + 1) * F + c4);
        float2* d = Wq + k2 * F + c4;
        d[0] = make_float2(a.x, b.x);
        d[1] = make_float2(a.y, b.y);
        d[2] = make_float2(a.z, b.z);
        d[3] = make_float2(a.w, b.w);
    }
    // load X tile (coalesced float4, guarded)
    for (int i = t; i < ROWS * (K / 4); i += BS) {
        int r = i / (K / 4);
        int c = (i % (K / 4)) * 4;
        int gr = row0 + r;
        float4 v = (gr < NN) ? *(const float4*)(X + (size_t)gr * K + c)
                             : make_float4(0.f, 0.f, 0.f, 0.f);
        *(float4*)(Xs + r * XSTR + c) = v;
    }
    __syncthreads();

    const int ct = t % TC;
    const int rt = t / TC;
    const int rb = rt * RPT;

    unsigned long long acc[RPT][4];
#pragma unroll
    for (int r = 0; r < RPT; r++)
#pragma unroll
        for (int c = 0; c < 4; c++) acc[r][c] = 0ULL;

    const float*  xp = Xs + rb * XSTR;
    const float2* wp = Wq + ct;

#pragma unroll 2
    for (int k2 = 0; k2 < K / 2; k2++) {
        unsigned long long w0 = *(const unsigned long long*)(wp + 0 * TC);
        unsigned long long w1 = *(const unsigned long long*)(wp + 1 * TC);
        unsigned long long w2 = *(const unsigned long long*)(wp + 2 * TC);
        unsigned long long w3 = *(const unsigned long long*)(wp + 3 * TC);
        wp += F;
#pragma unroll
        for (int r = 0; r < RPT; r++) {
            unsigned long long xx =
                *(const unsigned long long*)(xp + r * XSTR + 2 * k2);
            ffma2(acc[r][0], xx, w0);
            ffma2(acc[r][1], xx, w1);
            ffma2(acc[r][2], xx, w2);
            ffma2(acc[r][3], xx, w3);
        }
    }

#pragma unroll
    for (int r = 0; r < RPT; r++) {
        int gr = row0 + rb + r;
        if (gr < NN) {
            float* op = out + (size_t)gr * F + ct;
#pragma unroll
            for (int c = 0; c < 4; c++) {
                float2 p = *(float2*)&acc[r][c];
                op[c * TC] = p.x + p.y;   // even-k + odd-k partials
            }
        }
    }
}

// ---- sparse aggregate: out[i] = dinv[i]*(dinv[i]h[i] + sum dinv[s]h[s]) + b --
// one warp per node; F=128 -> float4/lane, F=64 -> float2/lane; 4-edge batches
template <int F, bool RELU>
__global__ void k_agg(const float* __restrict__ g,
                      const float* __restrict__ bias,
                      float* __restrict__ out) {
    constexpr int VEC = F / 32;   // 4 or 2
    int wid  = (blockIdx.x * blockDim.x + threadIdx.x) >> 5;
    int lane = threadIdx.x & 31;
    if (wid >= NN) return;

    float di = g_dinv[wid];
    const float* self = g + (size_t)wid * F + lane * VEC;
    float a[VEC];
    if (VEC == 4) {
        float4 v = *(const float4*)self;
        a[0] = di * v.x; a[1] = di * v.y; a[2] = di * v.z; a[3] = di * v.w;
    } else {
        float2 v = *(const float2*)self;
        a[0] = di * v.x; a[1] = di * v.y;
    }

    int j = g_rowptr[wid];
    int e = g_rowptr[wid + 1];

    // 4-edge batches: independent loads -> MLP=4
    for (; j + 4 <= e; j += 4) {
        int s0 = g_col[j + 0];
        int s1 = g_col[j + 1];
        int s2 = g_col[j + 2];
        int s3 = g_col[j + 3];
        float d0 = g_dinv[s0], d1 = g_dinv[s1], d2 = g_dinv[s2], d3 = g_dinv[s3];
        const float* p0 = g + (size_t)s0 * F + lane * VEC;
        const float* p1 = g + (size_t)s1 * F + lane * VEC;
        const float* p2 = g + (size_t)s2 * F + lane * VEC;
        const float* p3 = g + (size_t)s3 * F + lane * VEC;
        if (VEC == 4) {
            float4 v0 = *(const float4*)p0;
            float4 v1 = *(const float4*)p1;
            float4 v2 = *(const float4*)p2;
            float4 v3 = *(const float4*)p3;
            a[0] = fmaf(d0, v0.x, a[0]); a[1] = fmaf(d0, v0.y, a[1]);
            a[2] = fmaf(d0, v0.z, a[2]); a[3] = fmaf(d0, v0.w, a[3]);
            a[0] = fmaf(d1, v1.x, a[0]); a[1] = fmaf(d1, v1.y, a[1]);
            a[2] = fmaf(d1, v1.z, a[2]); a[3] = fmaf(d1, v1.w, a[3]);
            a[0] = fmaf(d2, v2.x, a[0]); a[1] = fmaf(d2, v2.y, a[1]);
            a[2] = fmaf(d2, v2.z, a[2]); a[3] = fmaf(d2, v2.w, a[3]);
            a[0] = fmaf(d3, v3.x, a[0]); a[1] = fmaf(d3, v3.y, a[1]);
            a[2] = fmaf(d3, v3.z, a[2]); a[3] = fmaf(d3, v3.w, a[3]);
        } else {
            float2 v0 = *(const float2*)p0;
            float2 v1 = *(const float2*)p1;
            float2 v2 = *(const float2*)p2;
            float2 v3 = *(const float2*)p3;
            a[0] = fmaf(d0, v0.x, a[0]); a[1] = fmaf(d0, v0.y, a[1]);
            a[0] = fmaf(d1, v1.x, a[0]); a[1] = fmaf(d1, v1.y, a[1]);
            a[0] = fmaf(d2, v2.x, a[0]); a[1] = fmaf(d2, v2.y, a[1]);
            a[0] = fmaf(d3, v3.x, a[0]); a[1] = fmaf(d3, v3.y, a[1]);
        }
    }
    for (; j < e; j++) {
        int s = g_col[j];
        float d = g_dinv[s];
        const float* p = g + (size_t)s * F + lane * VEC;
        if (VEC == 4) {
            float4 v = *(const float4*)p;
            a[0] = fmaf(d, v.x, a[0]); a[1] = fmaf(d, v.y, a[1]);
            a[2] = fmaf(d, v.z, a[2]); a[3] = fmaf(d, v.w, a[3]);
        } else {
            float2 v = *(const float2*)p;
            a[0] = fmaf(d, v.x, a[0]); a[1] = fmaf(d, v.y, a[1]);
        }
    }

    float* op = out + (size_t)wid * F + lane * VEC;
    if (VEC == 4) {
        float4 b = *(const float4*)(bias + lane * 4);
        float4 o = make_float4(a[0] * di + b.x, a[1] * di + b.y,
                               a[2] * di + b.z, a[3] * di + b.w);
        if (RELU) {
            o.x = fmaxf(o.x, 0.f); o.y = fmaxf(o.y, 0.f);
            o.z = fmaxf(o.z, 0.f); o.w = fmaxf(o.w, 0.f);
        }
        *(float4*)op = o;
    } else {
        float2 b = *(const float2*)(bias + lane * 2);
        float2 o = make_float2(a[0] * di + b.x, a[1] * di + b.y);
        if (RELU) { o.x = fmaxf(o.x, 0.f); o.y = fmaxf(o.y, 0.f); }
        *(float2*)op = o;
    }
}

// ---------------- launch ----------------
extern "C" void kernel_launch(void* const* d_in, const int* in_sizes, int n_in,
                              void* d_out, int out_size) {
    const float* x  = (const float*)d_in[0];
    const int*   ei = (const int*)d_in[1];     // [2, E] row-major
    const float* W1 = (const float*)d_in[2];
    const float* b1 = (const float*)d_in[3];
    const float* W2 = (const float*)d_in[4];
    const float* b2 = (const float*)d_in[5];
    float* out = (float*)d_out;

    const int* src = ei;
    const int* dst = ei + EE;

    const int SM1 = (128 * HIDD + 64 * (128 + 4)) * 4;   // 99,328 B
    const int SM2 = (128 * OUTD + 64 * (128 + 4)) * 4;   // 66,560 B
    cudaFuncSetAttribute(k_gemm<HIDD>,
                         cudaFuncAttributeMaxDynamicSharedMemorySize, SM1);
    cudaFuncSetAttribute(k_gemm<OUTD>,
                         cudaFuncAttributeMaxDynamicSharedMemorySize, SM2);

    const int gemm_grid = (NN + 63) / 64;          // 1563
    const int agg_grid  = (NN * 32 + 255) / 256;   // 12500

    // Launch order chosen so the ncu sample (observed: my launch index 3)
    // lands on the heavy GEMM. gemm1 is CSR-independent (dinv applied in agg).
    k_zero_deg<<<(NN + 255) / 256, 256>>>();                 // 0
    k_count<<<(EE + 255) / 256, 256>>>(dst);                 // 1
    k_partial<<<SCAN_NB, 256>>>();                           // 2
    k_gemm<HIDD><<<gemm_grid, 256, SM1>>>(x, W1, g_t1);      // 3  <- profile target
    k_scan_partial<<<1, 512>>>();                            // 4
    k_finalize<<<SCAN_NB, 256>>>();                          // 5
    k_fill<<<(EE + 255) / 256, 256>>>(src, dst);             // 6
    k_agg<HIDD, true><<<agg_grid, 256>>>(g_t1, b1, g_h);     // 7
    k_gemm<OUTD><<<gemm_grid, 256, SM2>>>(g_h, W2, g_t2);    // 8
    k_agg<OUTD, false><<<agg_grid, 256>>>(g_t2, b2, out);    // 9
}